// round 17
// baseline (speedup 1.0000x reference)
#include <cuda_runtime.h>

typedef unsigned long long u64;

#define HID 128
#define NA  1024
#define NR  1024

// Scratch: PA (bs1 folded in) and PR, row-major [row][h]
__device__ float g_PA[NA * HID];
__device__ float g_PR[NR * HID];

// ---------------- packed f32x2 helpers (sm_103a FADD2/FFMA2) ----------------
__device__ __forceinline__ u64 dup2(float v) {
    u64 d; asm("mov.b64 %0,{%1,%1};" : "=l"(d) : "f"(v)); return d;
}
__device__ __forceinline__ u64 pack2(float lo, float hi) {
    u64 d; asm("mov.b64 %0,{%1,%2};" : "=l"(d) : "f"(lo), "f"(hi)); return d;
}
__device__ __forceinline__ float2 unpack2(u64 d) {
    float2 r; asm("mov.b64 {%0,%1},%2;" : "=f"(r.x), "=f"(r.y) : "l"(d)); return r;
}
__device__ __forceinline__ u64 fadd2_(u64 a, u64 b) {
    u64 d; asm("add.rn.f32x2 %0,%1,%2;" : "=l"(d) : "l"(a), "l"(b)); return d;
}
__device__ __forceinline__ u64 ffma2_(u64 a, u64 b, u64 c) {
    u64 d; asm("fma.rn.f32x2 %0,%1,%2,%3;" : "=l"(d) : "l"(a), "l"(b), "l"(c)); return d;
}
__device__ __forceinline__ u64 relu2_(u64 x) {
    u64 d;
    asm("{\n\t.reg .f32 lo,hi;\n\t"
        "mov.b64 {lo,hi},%1;\n\t"
        "max.f32 lo,lo,0f00000000;\n\t"
        "max.f32 hi,hi,0f00000000;\n\t"
        "mov.b64 %0,{lo,hi};\n\t}"
        : "=l"(d) : "l"(x));
    return d;
}

// ---------------------------------------------------------------------------
// 128x128 MLP layer pass, f32x2 row-pairs, 8-deep register prefetch of the
// weight column. hT is [k][row-pair] (broadcast reads, conflict-free).
// (round-4 proven embed path)
// ---------------------------------------------------------------------------
__device__ __forceinline__ void mlp128(const float* __restrict__ Wp, int j, int pb,
                                       const u64 (*__restrict__ hT)[8], u64 acc[4])
{
    acc[0] = acc[1] = acc[2] = acc[3] = 0ull;
    float wA[8], wB[8];
    #pragma unroll
    for (int i = 0; i < 8; ++i) wA[i] = Wp[i * HID + j];
    #pragma unroll 1
    for (int kb = 0; kb < 128; kb += 16) {
        #pragma unroll
        for (int i = 0; i < 8; ++i) wB[i] = Wp[(kb + 8 + i) * HID + j];
        #pragma unroll
        for (int i = 0; i < 8; ++i) {
            int k = kb + i;
            u64 w2 = dup2(wA[i]);
            ulonglong2 x01 = *(const ulonglong2*)&hT[k][pb];
            ulonglong2 x23 = *(const ulonglong2*)&hT[k][pb + 2];
            acc[0] = ffma2_(x01.x, w2, acc[0]);
            acc[1] = ffma2_(x01.y, w2, acc[1]);
            acc[2] = ffma2_(x23.x, w2, acc[2]);
            acc[3] = ffma2_(x23.y, w2, acc[3]);
        }
        #pragma unroll
        for (int i = 0; i < 8; ++i)
            wA[i] = (kb + 16 + i < 128) ? Wp[(kb + 16 + i) * HID + j] : 0.f;
        #pragma unroll
        for (int i = 0; i < 8; ++i) {
            int k = kb + 8 + i;
            u64 w2 = dup2(wB[i]);
            ulonglong2 x01 = *(const ulonglong2*)&hT[k][pb];
            ulonglong2 x23 = *(const ulonglong2*)&hT[k][pb + 2];
            acc[0] = ffma2_(x01.x, w2, acc[0]);
            acc[1] = ffma2_(x01.y, w2, acc[1]);
            acc[2] = ffma2_(x23.x, w2, acc[2]);
            acc[3] = ffma2_(x23.y, w2, acc[3]);
        }
    }
}

// ---------------------------------------------------------------------------
// Kernel 1: fused MLP chain. 128 blocks (64 agent + 64 region) x 256 threads,
// 16 rows per block. j = t&127 (column), half = t>>7 picks 4 of 8 row-pairs.
// (round-4 proven config)
// ---------------------------------------------------------------------------
__global__ __launch_bounds__(256) void embed_kernel(
    const float* __restrict__ xa,  const float* __restrict__ xr,
    const float* __restrict__ Wa1, const float* __restrict__ ba1,
    const float* __restrict__ Wa2, const float* __restrict__ ba2,
    const float* __restrict__ Wr1, const float* __restrict__ br1,
    const float* __restrict__ Wr2, const float* __restrict__ br2,
    const float* __restrict__ Ws1, const float* __restrict__ bs1)
{
    const int ROWS = 16;
    int blk = blockIdx.x;
    bool agent = blk < 64;
    int rbase = (agent ? blk : blk - 64) * ROWS;
    int idim = agent ? 24 : 20;
    const float* x  = agent ? (xa + rbase * 24) : (xr + rbase * 20);
    const float* W1 = agent ? Wa1 : Wr1;
    const float* b1 = agent ? ba1 : br1;
    const float* W2 = agent ? Wa2 : Wr2;
    const float* b2 = agent ? ba2 : br2;
    const float* Ws = agent ? Ws1 : (Ws1 + HID * HID);
    float* outp = agent ? g_PA : g_PR;

    __shared__ __align__(16) u64 xsp[24][8];   // packed input [k][row-pair]
    __shared__ __align__(16) u64 hT[HID][8];   // packed activ [k][row-pair]

    int t = threadIdx.x;
    int j = t & 127;
    int pb = (t >> 7) * 4;     // row-pair base (0 or 4)

    // Stage packed input rows
    for (int i = t; i < idim * 8; i += 256) {
        int k = i >> 3, p = i & 7;
        xsp[k][p] = pack2(x[(2 * p) * idim + k], x[(2 * p + 1) * idim + k]);
    }
    __syncthreads();

    // Layer 1
    u64 acc[4];
    {
        u64 bp = dup2(b1[j]);
        acc[0] = acc[1] = acc[2] = acc[3] = bp;
        #pragma unroll 4
        for (int k = 0; k < idim; ++k) {
            u64 w2 = dup2(W1[k * HID + j]);
            ulonglong2 x01 = *(const ulonglong2*)&xsp[k][pb];
            ulonglong2 x23 = *(const ulonglong2*)&xsp[k][pb + 2];
            acc[0] = ffma2_(x01.x, w2, acc[0]);
            acc[1] = ffma2_(x01.y, w2, acc[1]);
            acc[2] = ffma2_(x23.x, w2, acc[2]);
            acc[3] = ffma2_(x23.y, w2, acc[3]);
        }
        #pragma unroll
        for (int p = 0; p < 4; ++p) hT[j][pb + p] = relu2_(acc[p]);
    }
    __syncthreads();

    // Layer 2
    mlp128(W2, j, pb, hT, acc);
    {
        u64 b2d = dup2(b2[j]);
        __syncthreads();             // all hT reads done before overwrite
        #pragma unroll
        for (int p = 0; p < 4; ++p)
            hT[j][pb + p] = relu2_(fadd2_(acc[p], b2d));
    }
    __syncthreads();

    // Score projection
    mlp128(Ws, j, pb, hT, acc);
    u64 bsd = agent ? dup2(bs1[j]) : 0ull;
    #pragma unroll
    for (int p = 0; p < 4; ++p) {
        u64 v = agent ? fadd2_(acc[p], bsd) : acc[p];
        float2 f = unpack2(v);
        int row = rbase + 2 * (pb + p);
        outp[row * HID + j]       = f.x;
        outp[(row + 1) * HID + j] = f.y;
    }
}

// ---------------------------------------------------------------------------
// Kernel 2: pairwise scores via the abs identity:
//   relu(t)*w = t*(w/2) + |t|*(w/2),  t = pa + pr
// The linear part factors: sum_h t*wh = C_a + D_r (per-row dots, computed
// per block from the staged tiles). Inner loop keeps only sum_h |t|*wh:
//   FADD + FFMA(|src| modifier, free) = 2 fma-pipe issues per lane. No movs,
// no packed asm. Block tile 64a x 32r, 128 threads, 4a x 4r per thread
// (a = ty+16i, r = tx+8jj). Pitch 68 floats (conflict-free). Grid 512.
// ---------------------------------------------------------------------------
__global__ __launch_bounds__(128, 6) void pair_kernel(
    const float* __restrict__ Ws2, const float* __restrict__ bs2,
    float* __restrict__ out)
{
    __shared__ __align__(16) float As[64 * 68];   // [a][h_local], 17.4KB
    __shared__ __align__(16) float Rs[32 * 68];   // [r][h_local],  8.7KB
    __shared__ __align__(16) float wh[HID];       // Ws2 * 0.5
    __shared__ float Cs[64];                      // C_a = sum pa*wh
    __shared__ float Ds[32];                      // D_r = sum pr*wh

    int t  = threadIdx.x;
    int tx = t & 7;          // r = tx + 8*jj
    int ty = t >> 3;         // a = ty + 16*i   (ty 0..15)
    int a0 = blockIdx.y * 64;
    int r0 = blockIdx.x * 32;

    wh[t] = Ws2[t] * 0.5f;   // exact (power-of-2 scale)

    float acc[4][4];
    #pragma unroll
    for (int i = 0; i < 4; ++i)
        #pragma unroll
        for (int jj = 0; jj < 4; ++jj) acc[i][jj] = 0.f;

    float cd = 0.f;          // this thread's C_a (t<64) or D_r (64<=t<96)

    for (int c = 0; c < 2; ++c) {
        int hb = 64 * c;
        __syncthreads();   // previous chunk's reads done (and wh on c==0)

        #pragma unroll
        for (int it = 0; it < 8; ++it) {
            int idx = t + 128 * it;
            int row = idx >> 4, c4 = idx & 15;
            *(float4*)&As[row * 68 + 4 * c4] =
                *(const float4*)&g_PA[(size_t)(a0 + row) * HID + hb + 4 * c4];
        }
        #pragma unroll
        for (int it = 0; it < 4; ++it) {
            int idx = t + 128 * it;
            int row = idx >> 4, c4 = idx & 15;
            *(float4*)&Rs[row * 68 + 4 * c4] =
                *(const float4*)&g_PR[(size_t)(r0 + row) * HID + hb + 4 * c4];
        }
        __syncthreads();

        // Per-row linear dots: C_a / D_r partial for this 64-h chunk.
        if (t < 96) {
            const float* rowp = (t < 64) ? &As[t * 68] : &Rs[(t - 64) * 68];
            #pragma unroll
            for (int h4 = 0; h4 < 16; ++h4) {
                float4 v  = *(const float4*)&rowp[4 * h4];
                float4 w4 = *(const float4*)&wh[hb + 4 * h4];
                cd = fmaf(v.x, w4.x, cd);
                cd = fmaf(v.y, w4.y, cd);
                cd = fmaf(v.z, w4.z, cd);
                cd = fmaf(v.w, w4.w, cd);
            }
        }

        // Main: acc += |a + r| * wh   (FADD + FFMA with free |.|)
        #pragma unroll 2
        for (int hd = 0; hd < 16; ++hd) {
            float4 w4 = *(const float4*)&wh[hb + 4 * hd];
            float4 av[4], rv[4];
            #pragma unroll
            for (int i = 0; i < 4; ++i)
                av[i] = *(const float4*)&As[(ty + 16 * i) * 68 + 4 * hd];
            #pragma unroll
            for (int jj = 0; jj < 4; ++jj)
                rv[jj] = *(const float4*)&Rs[(tx + 8 * jj) * 68 + 4 * hd];
            #pragma unroll
            for (int i = 0; i < 4; ++i)
                #pragma unroll
                for (int jj = 0; jj < 4; ++jj) {
                    acc[i][jj] = fmaf(fabsf(av[i].x + rv[jj].x), w4.x, acc[i][jj]);
                    acc[i][jj] = fmaf(fabsf(av[i].y + rv[jj].y), w4.y, acc[i][jj]);
                    acc[i][jj] = fmaf(fabsf(av[i].z + rv[jj].z), w4.z, acc[i][jj]);
                    acc[i][jj] = fmaf(fabsf(av[i].w + rv[jj].w), w4.w, acc[i][jj]);
                }
        }
    }

    if (t < 64)       Cs[t]      = cd;
    else if (t < 96)  Ds[t - 64] = cd;
    __syncthreads();

    float b = *bs2;
    #pragma unroll
    for (int i = 0; i < 4; ++i) {
        int a = a0 + ty + 16 * i;
        float ca = Cs[ty + 16 * i];
        #pragma unroll
        for (int jj = 0; jj < 4; ++jj)
            out[(size_t)a * NR + r0 + tx + 8 * jj] =
                acc[i][jj] + ca + Ds[tx + 8 * jj] + b;
    }
}

// ---------------------------------------------------------------------------
extern "C" void kernel_launch(void* const* d_in, const int* in_sizes, int n_in,
                              void* d_out, int out_size)
{
    const float* xa  = (const float*)d_in[0];
    const float* xr  = (const float*)d_in[1];
    const float* Wa1 = (const float*)d_in[2];
    const float* ba1 = (const float*)d_in[3];
    const float* Wa2 = (const float*)d_in[4];
    const float* ba2 = (const float*)d_in[5];
    const float* Wr1 = (const float*)d_in[6];
    const float* br1 = (const float*)d_in[7];
    const float* Wr2 = (const float*)d_in[8];
    const float* br2 = (const float*)d_in[9];
    const float* Ws1 = (const float*)d_in[10];
    const float* bs1 = (const float*)d_in[11];
    const float* Ws2 = (const float*)d_in[12];
    const float* bs2 = (const float*)d_in[13];
    float* out = (float*)d_out;

    embed_kernel<<<128, 256>>>(xa, xr, Wa1, ba1, Wa2, ba2,
                               Wr1, br1, Wr2, br2, Ws1, bs1);
    pair_kernel<<<dim3(NR / 32, NA / 64), 128>>>(Ws2, bs2, out);
}